// round 11
// baseline (speedup 1.0000x reference)
#include <cuda_runtime.h>
#include <cstdint>

// StructAttentionLayer: B=16384, A=50, D=256, fp32. HBM-bound (873MB, read once).
// R11 = R10 skeleton (non-persistent, 1 tile/CTA, 52KB SMEM, 4 slots/SM,
// evict_first TMA, __stcs stores) + STREAMING SOFTMAX: q=exp(leakyrelu(e)) is
// computed per 13-row chunk as its TMA lands, and the weighted sum for that
// chunk is accumulated immediately (normalization deferred to a final scalar
// A/Σq). Tail shrinks from ~0.65us (full softmax+full wsum) to ~0.25us
// (last chunk only), which is the term that bounds DRAM duty cycle.

#define A_NUM 50
#define D_DIM 256
#define ALPHA 0.2f
#define ENT_BYTES  (D_DIM * 4)             // 1024
#define TILE_BYTES (A_NUM * D_DIM * 4)     // 51200
#define DYN_SMEM   (TILE_BYTES + ENT_BYTES)

__global__ __launch_bounds__(256, 4)
void struct_attn_kernel(const float* __restrict__ attrs,
                        const float* __restrict__ ent,
                        const float* __restrict__ aa,
                        float* __restrict__ out)
{
    extern __shared__ __align__(128) float sm[];
    float* tile = sm;                          // tile[a*256 + d]
    float* ents = sm + A_NUM * D_DIM;          // ents[256]

    __shared__ float e_s[52];                  // unnormalized weights q[a]
    __shared__ __align__(8) unsigned long long mbar[5];  // [0]=ent, [1..4]=chunks

    const int b    = blockIdx.x;
    const int t    = threadIdx.x;
    const int warp = t >> 5;
    const int lane = t & 31;

    uint32_t mba[5];
#pragma unroll
    for (int i = 0; i < 5; i++)
        mba[i] = (uint32_t)__cvta_generic_to_shared(&mbar[i]);
    const uint32_t tile_a = (uint32_t)__cvta_generic_to_shared(tile);

    // Chunk layout: bases {0,13,26,39}, counts {13,13,13,11}.
    if (t == 0) {
#pragma unroll
        for (int i = 0; i < 5; i++)
            asm volatile("mbarrier.init.shared.b64 [%0], 1;" :: "r"(mba[i]) : "memory");
        asm volatile("fence.proxy.async.shared::cta;" ::: "memory");

        unsigned long long pol;
        asm volatile("createpolicy.fractional.L2::evict_first.b64 %0, 1.0;" : "=l"(pol));

        const float* gsrc = attrs + (size_t)b * (A_NUM * D_DIM);

        // Entity row FIRST (1KB — lands almost immediately).
        asm volatile("mbarrier.arrive.expect_tx.shared.b64 _, [%0], %1;"
                     :: "r"(mba[0]), "r"((uint32_t)ENT_BYTES) : "memory");
        asm volatile("cp.async.bulk.shared::cta.global.mbarrier::complete_tx::bytes"
                     ".L2::cache_hint [%0], [%1], %2, [%3], %4;"
                     :: "r"(tile_a + TILE_BYTES), "l"(ent + (size_t)b * D_DIM),
                        "r"((uint32_t)ENT_BYTES), "r"(mba[0]), "l"(pol) : "memory");

        // Four row chunks.
#pragma unroll
        for (int c = 0; c < 4; c++) {
            const uint32_t base = c * 13;
            const uint32_t rows = (c == 3) ? 11u : 13u;
            asm volatile("mbarrier.arrive.expect_tx.shared.b64 _, [%0], %1;"
                         :: "r"(mba[c + 1]), "r"(rows * 1024u) : "memory");
            asm volatile("cp.async.bulk.shared::cta.global.mbarrier::complete_tx::bytes"
                         ".L2::cache_hint [%0], [%1], %2, [%3], %4;"
                         :: "r"(tile_a + base * 1024u), "l"(gsrc + base * D_DIM),
                            "r"(rows * 1024u), "r"(mba[c + 1]), "l"(pol) : "memory");
        }
    }

    // Weight vectors (2KB, L2-resident) — overlap TMA latency.
    const float4* aa4 = reinterpret_cast<const float4*>(aa);
    const float4 aw0 = aa4[lane];            // a_attr cols 4*lane..
    const float4 aw1 = aa4[32 + lane];       // a_attr cols 128+4*lane..
    const float4 ew0 = aa4[64 + lane];       // a_ent
    const float4 ew1 = aa4[96 + lane];

    __syncthreads();   // mbarrier inits visible

#define WAIT_MB(MB)                                                             \
    asm volatile(                                                               \
        "{\n\t.reg .pred P;\n\t"                                                \
        "WL%=:\n\t"                                                             \
        "mbarrier.try_wait.parity.acquire.cta.shared::cta.b64 P, [%0], 0, 0x989680;\n\t" \
        "@P bra WD%=;\n\tbra WL%=;\n\tWD%=:\n\t}" :: "r"(MB) : "memory")

    // --- entity dot, computed redundantly by every warp (all lanes get ed) ---
    WAIT_MB(mba[0]);
    float ed;
    {
        const float4* e4 = reinterpret_cast<const float4*>(ents);
        const float4 ev0 = e4[lane];
        const float4 ev1 = e4[32 + lane];
        float p = ev0.x * ew0.x + ev0.y * ew0.y + ev0.z * ew0.z + ev0.w * ew0.w
                + ev1.x * ew1.x + ev1.y * ew1.y + ev1.z * ew1.z + ev1.w * ew1.w;
        p += __shfl_xor_sync(0xffffffffu, p, 16);
        p += __shfl_xor_sync(0xffffffffu, p, 8);
        p += __shfl_xor_sync(0xffffffffu, p, 4);
        p += __shfl_xor_sync(0xffffffffu, p, 2);
        p += __shfl_xor_sync(0xffffffffu, p, 1);
        ed = p;
    }

    const float4* tile4 = reinterpret_cast<const float4*>(tile);

    // Row logit -> unnormalized weight q, stored to e_s by lane 0.
#define ROW_Q(a)                                                                \
    do {                                                                        \
        const float4 v0 = tile4[(a) * 64 + lane];                               \
        const float4 v1 = tile4[(a) * 64 + 32 + lane];                          \
        float s = v0.x * aw0.x + v0.y * aw0.y + v0.z * aw0.z + v0.w * aw0.w     \
                + v1.x * aw1.x + v1.y * aw1.y + v1.z * aw1.z + v1.w * aw1.w;    \
        s += __shfl_xor_sync(0xffffffffu, s, 16);                               \
        s += __shfl_xor_sync(0xffffffffu, s, 8);                                \
        s += __shfl_xor_sync(0xffffffffu, s, 4);                                \
        s += __shfl_xor_sync(0xffffffffu, s, 2);                                \
        s += __shfl_xor_sync(0xffffffffu, s, 1);                                \
        if (lane == 0) {                                                        \
            float e = s + ed;                                                   \
            e = (e > 0.f) ? e : ALPHA * e;                                      \
            e_s[(a)] = __expf(e);                                               \
        }                                                                       \
    } while (0)

    float acc = 0.f, qsum = 0.f;

    // --- per-chunk: logits+exp -> barrier -> fused weighted-sum accumulate ---
#pragma unroll
    for (int c = 0; c < 4; c++) {
        const int base = c * 13;
        const int rows = (c == 3) ? 11 : 13;

        WAIT_MB(mba[c + 1]);
        // warp w owns rows base+w and base+w+8 (if inside chunk)
        if (warp < rows) ROW_Q(base + warp);
        if (warp + 8 < rows) ROW_Q(base + warp + 8);
        __syncthreads();   // e_s[base..base+rows) visible to all

        // fused weighted sum for this chunk: thread t owns column t
        for (int a = base; a < base + rows; a++) {
            const float q = e_s[a];            // broadcast LDS
            acc = fmaf(q, tile[a * D_DIM + t], acc);
            qsum += q;
        }
    }

    // --- final deferred normalization + streaming store ---
    __stcs(out + (size_t)b * D_DIM + t, acc * ((float)A_NUM / qsum));
#undef WAIT_MB
#undef ROW_Q
}

extern "C" void kernel_launch(void* const* d_in, const int* in_sizes, int n_in,
                              void* d_out, int out_size)
{
    const float* attrs = (const float*)d_in[0];   // [16384, 50, 256]
    const float* ent   = (const float*)d_in[1];   // [16384, 256]
    const float* aa    = (const float*)d_in[2];   // [512, 1]
    float* out         = (float*)d_out;           // [16384, 256]

    static int attr_set = 0;
    if (!attr_set) {
        cudaFuncSetAttribute(struct_attn_kernel,
                             cudaFuncAttributeMaxDynamicSharedMemorySize, DYN_SMEM);
        attr_set = 1;
    }

    const int B = in_sizes[1] / D_DIM;            // 16384
    struct_attn_kernel<<<B, 256, DYN_SMEM>>>(attrs, ent, aa, out);
}

// round 12
// speedup vs baseline: 1.0519x; 1.0519x over previous
#include <cuda_runtime.h>
#include <cstdint>

// StructAttentionLayer: B=16384, A=50, D=256, fp32. HBM-bound (873MB, read once).
// R12 = R10 skeleton (non-persistent, 1 tile/CTA, 52KB SMEM, 4 slots/SM,
// evict_first TMA, __stcs stores) + deferred-normalization softmax at 2-chunk
// granularity: chunk A's weighted sum is accumulated WHILE chunk B streams;
// the per-slot tail is only chunk B's 24-row logits+wsum + a scalar scale.
//   q[a] = exp(leakyrelu(e[a]))  (no max shift; logits are O(10), fp32-safe;
//   validated rel_err ~3e-7 in R11), out = (A/Σq) * Σ q[a]·attrs[a,:].

#define A_NUM 50
#define D_DIM 256
#define ALPHA 0.2f
#define ROWS_A 26
#define ROWS_B (A_NUM - ROWS_A)                 // 24
#define CHUNKA_BYTES (ROWS_A * D_DIM * 4)       // 26624
#define CHUNKB_BYTES (ROWS_B * D_DIM * 4)       // 24576
#define ENT_BYTES    (D_DIM * 4)                // 1024
#define TILE_BYTES   (A_NUM * D_DIM * 4)        // 51200
#define DYN_SMEM     (TILE_BYTES + ENT_BYTES)   // 52224

__global__ __launch_bounds__(256, 4)
void struct_attn_kernel(const float* __restrict__ attrs,
                        const float* __restrict__ ent,
                        const float* __restrict__ aa,
                        float* __restrict__ out)
{
    extern __shared__ __align__(128) float sm[];
    float* tile = sm;                          // tile[a*256 + d]
    float* ents = sm + A_NUM * D_DIM;          // ents[256]

    __shared__ float e_s[52];                  // unnormalized weights q[a]
    __shared__ __align__(8) unsigned long long mbar[3];  // [0]=ent, [1]=A, [2]=B

    const int b    = blockIdx.x;
    const int t    = threadIdx.x;
    const int warp = t >> 5;
    const int lane = t & 31;

    const uint32_t mbE = (uint32_t)__cvta_generic_to_shared(&mbar[0]);
    const uint32_t mbA = (uint32_t)__cvta_generic_to_shared(&mbar[1]);
    const uint32_t mbB = (uint32_t)__cvta_generic_to_shared(&mbar[2]);
    const uint32_t tile_a = (uint32_t)__cvta_generic_to_shared(tile);

    if (t == 0) {
        asm volatile("mbarrier.init.shared.b64 [%0], 1;" :: "r"(mbE) : "memory");
        asm volatile("mbarrier.init.shared.b64 [%0], 1;" :: "r"(mbA) : "memory");
        asm volatile("mbarrier.init.shared.b64 [%0], 1;" :: "r"(mbB) : "memory");
        asm volatile("fence.proxy.async.shared::cta;" ::: "memory");

        unsigned long long pol;
        asm volatile("createpolicy.fractional.L2::evict_first.b64 %0, 1.0;" : "=l"(pol));

        const float* gsrc = attrs + (size_t)b * (A_NUM * D_DIM);

        // Entity row first (1KB, lands almost immediately).
        asm volatile("mbarrier.arrive.expect_tx.shared.b64 _, [%0], %1;"
                     :: "r"(mbE), "r"((uint32_t)ENT_BYTES) : "memory");
        asm volatile("cp.async.bulk.shared::cta.global.mbarrier::complete_tx::bytes"
                     ".L2::cache_hint [%0], [%1], %2, [%3], %4;"
                     :: "r"(tile_a + TILE_BYTES), "l"(ent + (size_t)b * D_DIM),
                        "r"((uint32_t)ENT_BYTES), "r"(mbE), "l"(pol) : "memory");
        // Chunk A: rows 0..25
        asm volatile("mbarrier.arrive.expect_tx.shared.b64 _, [%0], %1;"
                     :: "r"(mbA), "r"((uint32_t)CHUNKA_BYTES) : "memory");
        asm volatile("cp.async.bulk.shared::cta.global.mbarrier::complete_tx::bytes"
                     ".L2::cache_hint [%0], [%1], %2, [%3], %4;"
                     :: "r"(tile_a), "l"(gsrc),
                        "r"((uint32_t)CHUNKA_BYTES), "r"(mbA), "l"(pol) : "memory");
        // Chunk B: rows 26..49
        asm volatile("mbarrier.arrive.expect_tx.shared.b64 _, [%0], %1;"
                     :: "r"(mbB), "r"((uint32_t)CHUNKB_BYTES) : "memory");
        asm volatile("cp.async.bulk.shared::cta.global.mbarrier::complete_tx::bytes"
                     ".L2::cache_hint [%0], [%1], %2, [%3], %4;"
                     :: "r"(tile_a + CHUNKA_BYTES), "l"(gsrc + ROWS_A * D_DIM),
                        "r"((uint32_t)CHUNKB_BYTES), "r"(mbB), "l"(pol) : "memory");
    }

    // Weight vectors (2KB, L2-resident) — overlap TMA latency.
    const float4* aa4 = reinterpret_cast<const float4*>(aa);
    const float4 aw0 = aa4[lane];            // a_attr cols 4*lane..
    const float4 aw1 = aa4[32 + lane];       // a_attr cols 128+4*lane..
    const float4 ew0 = aa4[64 + lane];       // a_ent
    const float4 ew1 = aa4[96 + lane];

    __syncthreads();   // mbarrier inits visible

#define WAIT_MB(MB)                                                             \
    asm volatile(                                                               \
        "{\n\t.reg .pred P;\n\t"                                                \
        "WL%=:\n\t"                                                             \
        "mbarrier.try_wait.parity.acquire.cta.shared::cta.b64 P, [%0], 0, 0x989680;\n\t" \
        "@P bra WD%=;\n\tbra WL%=;\n\tWD%=:\n\t}" :: "r"(MB) : "memory")

    // --- entity dot, computed redundantly by every warp (all lanes get ed) ---
    WAIT_MB(mbE);
    float ed;
    {
        const float4* e4 = reinterpret_cast<const float4*>(ents);
        const float4 ev0 = e4[lane];
        const float4 ev1 = e4[32 + lane];
        float p = ev0.x * ew0.x + ev0.y * ew0.y + ev0.z * ew0.z + ev0.w * ew0.w
                + ev1.x * ew1.x + ev1.y * ew1.y + ev1.z * ew1.z + ev1.w * ew1.w;
        p += __shfl_xor_sync(0xffffffffu, p, 16);
        p += __shfl_xor_sync(0xffffffffu, p, 8);
        p += __shfl_xor_sync(0xffffffffu, p, 4);
        p += __shfl_xor_sync(0xffffffffu, p, 2);
        p += __shfl_xor_sync(0xffffffffu, p, 1);
        ed = p;
    }

    const float4* tile4 = reinterpret_cast<const float4*>(tile);

    // Row logit -> unnormalized weight q = exp(leakyrelu(s+ed)), via lane 0.
#define ROW_Q(a)                                                                \
    do {                                                                        \
        const float4 v0 = tile4[(a) * 64 + lane];                               \
        const float4 v1 = tile4[(a) * 64 + 32 + lane];                          \
        float s = v0.x * aw0.x + v0.y * aw0.y + v0.z * aw0.z + v0.w * aw0.w     \
                + v1.x * aw1.x + v1.y * aw1.y + v1.z * aw1.z + v1.w * aw1.w;    \
        s += __shfl_xor_sync(0xffffffffu, s, 16);                               \
        s += __shfl_xor_sync(0xffffffffu, s, 8);                                \
        s += __shfl_xor_sync(0xffffffffu, s, 4);                                \
        s += __shfl_xor_sync(0xffffffffu, s, 2);                                \
        s += __shfl_xor_sync(0xffffffffu, s, 1);                                \
        if (lane == 0) {                                                        \
            float e = s + ed;                                                   \
            e = (e > 0.f) ? e : ALPHA * e;                                      \
            e_s[(a)] = __expf(e);                                               \
        }                                                                       \
    } while (0)

    // --- chunk A: rows 0..25. warp w: rows w, w+8, w+16; warps 0,1 also w+24 ---
    WAIT_MB(mbA);
    ROW_Q(warp);
    ROW_Q(warp + 8);
    ROW_Q(warp + 16);
    if (warp < 2) ROW_Q(warp + 24);
    __syncthreads();   // e_s[0..25] ready

    // --- chunk-A weighted sum, hidden under chunk B's stream ---
    float acc0 = 0.f, acc1 = 0.f, qsum = 0.f;
#pragma unroll
    for (int a = 0; a < ROWS_A; a += 2) {
        const float q0 = e_s[a];
        const float q1 = e_s[a + 1];
        acc0 = fmaf(q0, tile[a * D_DIM + t],       acc0);
        acc1 = fmaf(q1, tile[(a + 1) * D_DIM + t], acc1);
        qsum += q0 + q1;
    }

    // --- chunk B: rows 26..49. warp w: rows 26+w, 34+w, 42+w (24 rows) ---
    WAIT_MB(mbB);
    ROW_Q(26 + warp);
    ROW_Q(34 + warp);
    ROW_Q(42 + warp);
    __syncthreads();   // e_s[26..49] ready

#pragma unroll
    for (int a = ROWS_A; a < A_NUM; a += 2) {
        const float q0 = e_s[a];
        const float q1 = e_s[a + 1];
        acc0 = fmaf(q0, tile[a * D_DIM + t],       acc0);
        acc1 = fmaf(q1, tile[(a + 1) * D_DIM + t], acc1);
        qsum += q0 + q1;
    }

    // --- deferred normalization + streaming store ---
    __stcs(out + (size_t)b * D_DIM + t, (acc0 + acc1) * ((float)A_NUM / qsum));
#undef WAIT_MB
#undef ROW_Q
}

extern "C" void kernel_launch(void* const* d_in, const int* in_sizes, int n_in,
                              void* d_out, int out_size)
{
    const float* attrs = (const float*)d_in[0];   // [16384, 50, 256]
    const float* ent   = (const float*)d_in[1];   // [16384, 256]
    const float* aa    = (const float*)d_in[2];   // [512, 1]
    float* out         = (float*)d_out;           // [16384, 256]

    static int attr_set = 0;
    if (!attr_set) {
        cudaFuncSetAttribute(struct_attn_kernel,
                             cudaFuncAttributeMaxDynamicSharedMemorySize, DYN_SMEM);
        attr_set = 1;
    }

    const int B = in_sizes[1] / D_DIM;            // 16384
    struct_attn_kernel<<<B, 256, DYN_SMEM>>>(attrs, ent, aa, out);
}